// round 16
// baseline (speedup 1.0000x reference)
#include <cuda_runtime.h>
#include <cuda_bf16.h>
#include <cstdint>
#include <math.h>

// ---------------- problem constants ----------------
constexpr int CB  = 4;      // batch
constexpr int CC  = 512;    // channels
constexpr int CHH = 32;     // H
constexpr int CWW = 32;     // W
constexpr int CHW = 1024;   // H*W
constexpr int CNH = 8;      // heads
constexpr int NPR = 8;      // prompt tokens
constexpr int CN  = 1032;   // total tokens
constexpr int HID = 1024;   // mlp hidden
constexpr int QKV = 3*CC;   // fused qkv row stride
constexpr float EPS = 1e-5f;

// weight arena offsets (bf16 elements)
constexpr int OPG  = 0;
constexpr int OQKV = 262144;
constexpr int OWO  = OQKV + 3*262144;
constexpr int OW1  = OWO + 262144;
constexpr int OW2  = OW1 + 524288;
constexpr int OWOP = OW2 + 524288;
constexpr int WALL = OWOP + 262144;

// ---------------- scratch ----------------
__device__ __align__(16) float g_ppool[CB*NPR*8*CC];
__device__ __align__(16) float g_ds  [CB*CHW];
__device__ __align__(16) float g_jd  [CB*CN];
__device__ __align__(16) float g_jt  [CB*CN*CC];
__device__ __align__(16) __nv_bfloat16 g_pp1t_bf[CB*CHW*CC];
__device__ __align__(16) __nv_bfloat16 g_pp2t_bf[CB*CHW*CC];
__device__ __align__(16) __nv_bfloat16 g_x_bf  [CB*CN*CC];
__device__ __align__(16) __nv_bfloat16 g_qkv_bf[CB*CN*QKV];
__device__ __align__(16) __nv_bfloat16 g_ao_bf [CB*CN*CC];
__device__ __align__(16) __nv_bfloat16 g_h_bf  [CB*CN*HID];
__device__ __align__(16) __nv_bfloat16 g_enh_bf[CB*CC*CHW];
__device__ __align__(16) __nv_bfloat16 g_o1t_bf[CB*CHW*CC];
__device__ __align__(16) __nv_bfloat16 g_o2t_bf[CB*CHW*CC];
__device__ __align__(16) __nv_bfloat16 g_wall  [WALL];

__device__ __forceinline__ float gelu_f(float x){
    return 0.5f * x * (1.0f + erff(x * 0.70710678118654752f));
}
__device__ __forceinline__ unsigned pack_bf(float lo, float hi){
    unsigned r;
    asm("cvt.rn.bf16x2.f32 %0, %1, %2;" : "=r"(r) : "f"(hi), "f"(lo));
    return r;
}
__device__ __forceinline__ float ldf(const float* p){ return *p; }
__device__ __forceinline__ float ldf(const __nv_bfloat16* p){ return __bfloat162float(*p); }
__device__ __forceinline__ void mma_bf16(float& d0, float& d1, float& d2, float& d3,
                                         unsigned a0, unsigned a1, unsigned a2, unsigned a3,
                                         unsigned b0, unsigned b1)
{
    asm volatile("mma.sync.aligned.m16n8k16.row.col.f32.bf16.bf16.f32 "
                 "{%0,%1,%2,%3}, {%4,%5,%6,%7}, {%8,%9}, {%0,%1,%2,%3};"
                 : "+f"(d0), "+f"(d1), "+f"(d2), "+f"(d3)
                 : "r"(a0), "r"(a1), "r"(a2), "r"(a3), "r"(b0), "r"(b1));
}
__device__ __forceinline__ unsigned su32(const void* p){
    return (unsigned)__cvta_generic_to_shared(p);
}
__device__ __forceinline__ void ldsm4(unsigned& r0, unsigned& r1, unsigned& r2, unsigned& r3,
                                      unsigned addr){
    asm volatile("ldmatrix.sync.aligned.m8n8.x4.shared.b16 {%0,%1,%2,%3}, [%4];"
                 : "=r"(r0), "=r"(r1), "=r"(r2), "=r"(r3) : "r"(addr));
}
__device__ __forceinline__ void ldsm4t(unsigned& r0, unsigned& r1, unsigned& r2, unsigned& r3,
                                       unsigned addr){
    asm volatile("ldmatrix.sync.aligned.m8n8.x4.trans.shared.b16 {%0,%1,%2,%3}, [%4];"
                 : "=r"(r0), "=r"(r1), "=r"(r2), "=r"(r3) : "r"(addr));
}
__device__ __forceinline__ void cp16(unsigned dst, const void* src, bool v){
    int sz = v ? 16 : 0;
    asm volatile("cp.async.cg.shared.global [%0], [%1], 16, %2;" :: "r"(dst), "l"(src), "r"(sz));
}
__device__ __forceinline__ void cp_commit(){ asm volatile("cp.async.commit_group;"); }
template<int N>
__device__ __forceinline__ void cp_wait(){ asm volatile("cp.async.wait_group %0;" :: "n"(N)); }

// ---------------- single fused weight pack ----------------
__global__ void k_pack_all(const float* __restrict__ pg, const float* __restrict__ wq,
                           const float* __restrict__ wk, const float* __restrict__ wv,
                           const float* __restrict__ wo, const float* __restrict__ w1,
                           const float* __restrict__ w2, const float* __restrict__ wop,
                           __nv_bfloat16* __restrict__ d)
{
    int i = blockIdx.x * 256 + threadIdx.x;
    if (i >= WALL/4) return;
    int f = i * 4;
    const float* s; int base;
    if      (f < OQKV)              { s = pg;  base = OPG;  }
    else if (f < OQKV + 262144)     { s = wq;  base = OQKV; }
    else if (f < OQKV + 2*262144)   { s = wk;  base = OQKV + 262144; }
    else if (f < OWO)               { s = wv;  base = OQKV + 2*262144; }
    else if (f < OW1)               { s = wo;  base = OWO;  }
    else if (f < OW2)               { s = w1;  base = OW1;  }
    else if (f < OWOP)              { s = w2;  base = OW2;  }
    else                            { s = wop; base = OWOP; }
    float4 v = *(const float4*)(s + (f - base));
    *(uint2*)(d + f) = make_uint2(pack_bf(v.x, v.y), pack_bf(v.z, v.w));
}

// ------- fused depthwise 3x3 conv + BN + GELU + transpose-to-token (+ gp projection) -------
template<int DUAL, typename TIN>
__global__ void k_dwconv_t(const TIN* __restrict__ in,
                           const float* __restrict__ w1, const float* __restrict__ bn1,
                           __nv_bfloat16* __restrict__ out1t,
                           const float* __restrict__ w2, const float* __restrict__ bn2,
                           const float* __restrict__ gpw, float* __restrict__ ds)
{
    __shared__ float tile[32][33];
    __shared__ float red[8][33];
    int b = blockIdx.z;
    int p0 = blockIdx.x * 32, c0 = blockIdx.y * 32;
    int tx = threadIdx.x, ty = threadIdx.y;
    int p = p0 + tx, y = p >> 5, x = p & 31;
    float wsum = 0.f;
#pragma unroll
    for (int i = 0; i < 4; i++){
        int c = c0 + ty + i*8;
        const TIN* base = in + (((size_t)b*CC + c) << 10);
        float v[9];
#pragma unroll
        for (int ky = 0; ky < 3; ky++)
#pragma unroll
            for (int kx = 0; kx < 3; kx++){
                int yy = y + ky - 1, xx = x + kx - 1;
                v[ky*3+kx] = (yy >= 0 && yy < CHH && xx >= 0 && xx < CWW) ? ldf(base + yy*CWW + xx) : 0.f;
            }
        float a1 = 0.f;
#pragma unroll
        for (int k = 0; k < 9; k++) a1 += w1[c*9+k] * v[k];
        float s1 = bn1[c] * rsqrtf(bn1[3*CC+c] + EPS);
        a1 = a1 * s1 + bn1[CC+c] - bn1[2*CC+c] * s1;
        tile[ty + i*8][tx] = gelu_f(a1);
        if (DUAL){
            float a2 = 0.f;
#pragma unroll
            for (int k = 0; k < 9; k++) a2 += w2[c*9+k] * v[k];
            float s2 = bn2[c] * rsqrtf(bn2[3*CC+c] + EPS);
            a2 = a2 * s2 + bn2[CC+c] - bn2[2*CC+c] * s2;
            wsum += gpw[c] * gelu_f(a2);
        }
    }
    if (DUAL) red[ty][tx] = wsum;
    __syncthreads();
    if (DUAL && ty == 0){
        float s = 0.f;
#pragma unroll
        for (int z = 0; z < 8; z++) s += red[z][tx];
        atomicAdd(&ds[(b << 10) + p0 + tx], s);
    }
#pragma unroll
    for (int i = 0; i < 4; i++){
        int pp_ = p0 + ty + i*8;
        out1t[((size_t)b*CHW + pp_)*CC + c0 + tx] = __float2bfloat16(tile[tx][ty + i*8]);
    }
}

// ---------------- transposes ----------------
__global__ void k_cp_to_tok_f(const float* __restrict__ in, float* __restrict__ out,
                              int tokTotal, int tokOff)
{
    __shared__ float tile[32][33];
    int b = blockIdx.z;
    int p0 = blockIdx.x * 32, c0 = blockIdx.y * 32;
    int tx = threadIdx.x, ty = threadIdx.y;
#pragma unroll
    for (int i = 0; i < 4; i++){
        int c = c0 + ty + i*8;
        tile[ty + i*8][tx] = in[((size_t)b*CC + c)*CHW + p0 + tx];
    }
    __syncthreads();
#pragma unroll
    for (int i = 0; i < 4; i++){
        int p = p0 + ty + i*8;
        out[((size_t)b*tokTotal + tokOff + p)*CC + c0 + tx] = tile[tx][ty + i*8];
    }
}

__global__ void k_tok_to_cp(const float* __restrict__ in, __nv_bfloat16* __restrict__ out,
                            int tokTotal, int tokOff)
{
    __shared__ float tile[32][33];
    int b = blockIdx.z;
    int p0 = blockIdx.x * 32, c0 = blockIdx.y * 32;
    int tx = threadIdx.x, ty = threadIdx.y;
#pragma unroll
    for (int i = 0; i < 4; i++){
        int p = p0 + ty + i*8;
        tile[ty + i*8][tx] = in[((size_t)b*tokTotal + tokOff + p)*CC + c0 + tx];
    }
    __syncthreads();
#pragma unroll
    for (int i = 0; i < 4; i++){
        int c = c0 + ty + i*8;
        out[((size_t)b*CC + c)*CHW + p0 + tx] = __float2bfloat16(tile[tx][ty + i*8]);
    }
}

// ------------- tensor-core NT GEMM: 128x64 tile, bf16, cp.async, ldmatrix -------------
// warp w (0..7) computes rows [w*16, w*16+16) x all 64 cols.
constexpr int RSU   = 20;              // uints per 32-bf16 row (16 data + 4 pad)
constexpr int A_STG = 128*RSU;         // uints per A stage
constexpr int B_STG = 64*RSU;          // uints per B stage
constexpr int NSTG  = 3;
constexpr int GEMM_SMEM = NSTG*(A_STG + B_STG)*4;   // 46080 B

template<int EPI, int OBF>
__global__ void __launch_bounds__(256) k_gemm_bf(const __nv_bfloat16* __restrict__ A,
                                                 const __nv_bfloat16* __restrict__ Bw,
                                                 void* __restrict__ Cout,
                                                 int M, int N, int K,
                                                 const float* __restrict__ ep,
                                                 const float* __restrict__ res)
{
    extern __shared__ unsigned gsm[];
    unsigned* As = gsm;
    unsigned* Bs = gsm + NSTG*A_STG;
    unsigned as_u = su32(As), bs_u = su32(Bs);

    int tid  = threadIdx.x;
    int lane = tid & 31;
    int w    = tid >> 5;          // 0..7, M-slice
    int m0 = blockIdx.y * 128, n0 = blockIdx.x * 64;

    // loaders: A 512 chunks (2/thread), B 256 chunks (1/thread)
    int r0 = tid >> 2, c0 = (tid & 3);
    const char* Ap0 = (const char*)(A + (size_t)(m0 + r0)*K + c0*8);
    const char* Ap1 = (const char*)(A + (size_t)(m0 + r0 + 64)*K + c0*8);
    const char* Bp0 = (const char*)(Bw + (size_t)(n0 + r0)*K + c0*8);
    bool av0 = (m0 + r0) < M, av1 = (m0 + r0 + 64) < M;
    unsigned ad0 = as_u + ((r0*RSU + c0*4) << 2);
    unsigned ad1 = as_u + (((r0+64)*RSU + c0*4) << 2);
    unsigned bd0 = bs_u + ((r0*RSU + c0*4) << 2);
    bool bldr = (r0 < 64);        // threads 0..255 map r0 0..63 only for tid<256/4... r0 = tid>>2 in 0..63

    float acc[8][4];
#pragma unroll
    for (int nf = 0; nf < 8; nf++)
#pragma unroll
        for (int r = 0; r < 4; r++) acc[nf][r] = 0.f;

    int NK = K >> 5;

#pragma unroll
    for (int st = 0; st < NSTG-1; st++){
        unsigned soA = (st*A_STG) << 2;
        unsigned soB = (st*B_STG) << 2;
        size_t go = (size_t)(st*32) * 2;
        cp16(ad0 + soA, Ap0 + go, av0);
        cp16(ad1 + soA, Ap1 + go, av1);
        cp16(bd0 + soB, Bp0 + go, true);
        cp_commit();
    }

    int l7 = lane & 7;
    unsigned a_base, b_base[4];
    {
        int acol = ((lane >> 4) & 1) * 4;
        int ar = w*16 + l7 + ((lane >> 3) & 1) * 8;
        a_base = as_u + ((ar*RSU + acol) << 2);
        int bcol = ((lane >> 3) & 1) * 4;
        int brr  = l7 + (lane >> 4) * 8;
#pragma unroll
        for (int nf2 = 0; nf2 < 4; nf2++)
            b_base[nf2] = bs_u + (((brr + nf2*16)*RSU + bcol) << 2);
    }

    for (int kt = 0; kt < NK; kt++){
        cp_wait<NSTG-2>();
        __syncthreads();

        int nk = kt + NSTG - 1;
        if (nk < NK){
            unsigned soA = ((nk % NSTG)*A_STG) << 2;
            unsigned soB = ((nk % NSTG)*B_STG) << 2;
            size_t go = (size_t)(nk*32) * 2;
            cp16(ad0 + soA, Ap0 + go, av0);
            cp16(ad1 + soA, Ap1 + go, av1);
            cp16(bd0 + soB, Bp0 + go, true);
        }
        cp_commit();

        unsigned soffA = ((unsigned)(kt % NSTG) * A_STG) << 2;
        unsigned soffB = ((unsigned)(kt % NSTG) * B_STG) << 2;
#pragma unroll
        for (int kf = 0; kf < 2; kf++){
            unsigned ko = kf*32;
            unsigned a0, a1, a2, a3;
            ldsm4(a0, a1, a2, a3, a_base + soffA + ko);
#pragma unroll
            for (int nf2 = 0; nf2 < 4; nf2++){
                unsigned b0, b1, b2, b3;
                ldsm4(b0, b1, b2, b3, b_base[nf2] + soffB + ko);
                mma_bf16(acc[nf2*2  ][0], acc[nf2*2  ][1], acc[nf2*2  ][2], acc[nf2*2  ][3],
                         a0, a1, a2, a3, b0, b1);
                mma_bf16(acc[nf2*2+1][0], acc[nf2*2+1][1], acc[nf2*2+1][2], acc[nf2*2+1][3],
                         a0, a1, a2, a3, b2, b3);
            }
        }
    }

#pragma unroll
    for (int ri = 0; ri < 2; ri++){
        int row = m0 + w*16 + (lane >> 2) + ri*8;
        if (row >= M) continue;
        size_t base = (size_t)row * N;
#pragma unroll
        for (int nf = 0; nf < 8; nf++){
            int col = n0 + nf*8 + 2*(lane & 3);
            float v0 = acc[nf][ri*2 + 0];
            float v1 = acc[nf][ri*2 + 1];
            if (EPI == 1){
                float s0 = ep[col]   * rsqrtf(ep[3*N+col]   + EPS);
                float s1 = ep[col+1] * rsqrtf(ep[3*N+col+1] + EPS);
                v0 = gelu_f(v0 * s0 + ep[N+col]   - ep[2*N+col]   * s0);
                v1 = gelu_f(v1 * s1 + ep[N+col+1] - ep[2*N+col+1] * s1);
            } else if (EPI == 2){
                v0 = gelu_f(v0 + ep[col]);
                v1 = gelu_f(v1 + ep[col+1]);
            } else if (EPI == 3){
                float2 rr2 = *(const float2*)(res + base + col);
                v0 = rr2.x + v0 + ep[col];
                v1 = rr2.y + v1 + ep[col+1];
            } else if (EPI == 4){
                float2 rr2 = *(const float2*)(res + base + col);
                v0 = rr2.x + v0;
                v1 = rr2.y + v1;
            }
            if (OBF){
                ((unsigned*)Cout)[(base + col) >> 1] = pack_bf(v0, v1);
            } else {
                *(float2*)((float*)Cout + base + col) = make_float2(v0, v1);
            }
        }
    }
    (void)bldr;
}

// ---------------- prompt pooling phase 1: partial sums (bf16 input) ----------------
__global__ void k_prompt_pool(const __nv_bfloat16* __restrict__ pp2t, float* __restrict__ pool)
{
    int chunk = blockIdx.x, pr = blockIdx.y, b = blockIdx.z;
    int iy = pr >> 2, ix = pr & 3;
    int t = threadIdx.x;
    float a0 = 0.f, a1 = 0.f;
#pragma unroll
    for (int py = 0; py < 2; py++)
#pragma unroll
        for (int px = 0; px < 8; px++){
            int p = (iy*16 + chunk*2 + py)*CWW + ix*8 + px;
            const __nv_bfloat16* base = pp2t + ((size_t)b*CHW + p)*CC;
            a0 += __bfloat162float(base[t]);
            a1 += __bfloat162float(base[t + 256]);
        }
    size_t o = (((size_t)(b*NPR + pr))*8 + chunk)*CC;
    pool[o + t]       = a0;
    pool[o + t + 256] = a1;
}

// ---------------- prompt phase 2: combine + embed + LN -> jt rows 0..7 ----------------
__global__ void k_prompt_ln(const float* __restrict__ pool, const float* __restrict__ pe,
                            const float* __restrict__ lnp, float* __restrict__ jt)
{
    int b = blockIdx.x >> 3, pr = blockIdx.x & 7;
    int t = threadIdx.x;
    const float* pb = pool + (((size_t)(b*NPR + pr))*8)*CC;
    float a0 = 0.f, a1 = 0.f;
#pragma unroll
    for (int ch = 0; ch < 8; ch++){
        a0 += pb[ch*CC + t];
        a1 += pb[ch*CC + t + 256];
    }
    a0 = a0 * (1.f/128.f) + pe[pr*CC + t];
    a1 = a1 * (1.f/128.f) + pe[pr*CC + t + 256];
    __shared__ float rs[256], rq[256];
    rs[t] = a0 + a1; rq[t] = a0*a0 + a1*a1;
    __syncthreads();
    for (int s = 128; s > 0; s >>= 1){
        if (t < s){ rs[t] += rs[t+s]; rq[t] += rq[t+s]; }
        __syncthreads();
    }
    float mean = rs[0] * (1.f/512.f);
    float var  = rq[0] * (1.f/512.f) - mean*mean;
    float inv  = rsqrtf(var + EPS);
    size_t o = ((size_t)b*CN + pr) * CC;
    jt[o + t]       = (a0 - mean) * inv * lnp[t]       + lnp[CC + t];
    jt[o + t + 256] = (a1 - mean) * inv * lnp[t + 256] + lnp[CC + t + 256];
}

// ---------------- joint depth scalar per token ----------------
__global__ void k_jd(const float* __restrict__ ds, const float* __restrict__ gpb,
                     float* __restrict__ jd)
{
    int t = blockIdx.x * 256 + threadIdx.x;
    if (t >= CB*CN) return;
    int b = t / CN, n = t % CN;
    float bias = gpb[0];
    if (n >= NPR){
        jd[t] = ds[b*CHW + (n - NPR)] + bias;
    } else {
        int iy = n >> 2, ix = n & 3;
        float acc = 0.f;
#pragma unroll
        for (int py = 0; py < 16; py++){
            const float4* r = (const float4*)(ds + b*CHW + (iy*16 + py)*CWW + ix*8);
            float4 v0 = r[0], v1 = r[1];
            acc += v0.x + v0.y + v0.z + v0.w + v1.x + v1.y + v1.z + v1.w;
        }
        jd[t] = acc * (1.f/128.f) + bias;
    }
}

// ---------------- layernorm over C per token (fp32 in, bf16 out) ----------------
__global__ void k_ln(const float* __restrict__ in, const float* __restrict__ p,
                     __nv_bfloat16* __restrict__ out)
{
    int tok = blockIdx.x;
    const float* row = in + (size_t)tok * CC;
    int t = threadIdx.x;
    float v0 = row[t], v1 = row[t + 256];
    __shared__ float rs[256], rq[256];
    rs[t] = v0 + v1; rq[t] = v0*v0 + v1*v1;
    __syncthreads();
    for (int s = 128; s > 0; s >>= 1){
        if (t < s){ rs[t] += rs[t+s]; rq[t] += rq[t+s]; }
        __syncthreads();
    }
    float mean = rs[0] * (1.f/512.f);
    float var  = rq[0] * (1.f/512.f) - mean*mean;
    float inv  = rsqrtf(var + EPS);
    size_t o = (size_t)tok * CC;
    out[o + t]       = __float2bfloat16((v0 - mean) * inv * p[t]       + p[CC + t]);
    out[o + t + 256] = __float2bfloat16((v1 - mean) * inv * p[t + 256] + p[CC + t + 256]);
}

// ---------------- attention: flash, bf16 mma.sync, ldmatrix, cp.async double-buffer --------
__device__ __forceinline__ void tok_coord(int n, float& cy, float& cx){
    if (n < NPR){ cy = (float)(n >> 2); cx = (float)(n & 3) * (1.f/3.f); }
    else { int m = n - NPR; cy = (float)(m >> 5) * (1.f/31.f); cx = (float)(m & 31) * (1.f/31.f); }
}

constexpr int AST  = 36;
constexpr int QS_OFF = 0;
constexpr int PS_OFF = 128*AST;
constexpr int KS_OFF = PS_OFF + 128*AST;
constexpr int STGK   = 64*AST;
constexpr int VS_OFF = KS_OFF + 2*STGK;
constexpr int KD_OFF = VS_OFF + 2*STGK;
constexpr int ATTN_SMEM = (KD_OFF + 128) * 4;

__global__ void __launch_bounds__(256) k_attn(const __nv_bfloat16* __restrict__ qkv,
                                              const float* __restrict__ jd,
                                              const float* __restrict__ gw,
                                              __nv_bfloat16* __restrict__ ao)
{
    extern __shared__ unsigned smu[];
    unsigned* Qs = smu + QS_OFF;
    unsigned* Ps = smu + PS_OFF;
    float*  kdep = (float*)(smu + KD_OFF);
    unsigned qs_u = su32(Qs), ps_u = su32(Ps);
    unsigned ks_u = su32(smu + KS_OFF), vs_u = su32(smu + VS_OFF);
    unsigned kd_u = su32(kdep);

    int b = blockIdx.z, h = blockIdx.y, q0 = blockIdx.x * 128;
    int tid = threadIdx.x, lane = tid & 31, w = tid >> 5;
    int c = lane & 3, gr = lane >> 2;

    const float decay = logf(1.f - exp2f(-1.f - 0.5f * (float)h));
    const float w0 = gw[0] * decay, w1 = gw[1] * decay;

#pragma unroll
    for (int j = 0; j < 4; j++){
        int i = tid + 256*j;
        int r = i >> 3, c4 = i & 7;
        int qn = q0 + r;
        uint4 v = (qn < CN) ? *(const uint4*)(qkv + ((size_t)b*CN + qn)*QKV + h*64 + c4*8)
                            : make_uint4(0,0,0,0);
        *(uint4*)&Qs[r*AST + c4*4] = v;
    }

    int lr = tid >> 3, lc = tid & 7;
    auto load_kv = [&](int kt){
        int k0 = kt * 64;
        unsigned st = (unsigned)(kt & 1);
#pragma unroll
        for (int j = 0; j < 2; j++){
            int r = lr + j*32;
            int n = k0 + r;
            bool val = (n < CN);
            const __nv_bfloat16* rowp = qkv + ((size_t)b*CN + n)*QKV + h*64;
            unsigned doff = st*STGK*4 + r*144 + lc*16;
            cp16(ks_u + doff, rowp + CC   + lc*8, val);
            cp16(vs_u + doff, rowp + 2*CC + lc*8, val);
        }
        if (tid < 16){
            bool val = (k0 + tid*4 + 4) <= CN;
            cp16(kd_u + st*256 + tid*16, jd + (size_t)b*CN + k0 + tid*4, val);
        }
        cp_commit();
    };

    float qy[2], qx[2], qd[2];
#pragma unroll
    for (int i = 0; i < 2; i++){
        int qn = q0 + w*16 + gr + i*8;
        if (qn < CN){ tok_coord(qn, qy[i], qx[i]); qd[i] = jd[b*CN + qn]; }
        else { qy[i] = qx[i] = qd[i] = 0.f; }
    }

    float O[8][4];
#pragma unroll
    for (int nf = 0; nf < 8; nf++)
#pragma unroll
        for (int r = 0; r < 4; r++) O[nf][r] = 0.f;
    float mi[2] = {-1e30f, -1e30f}, li[2] = {0.f, 0.f};

    unsigned q_base = qs_u + (w*16 + (lane & 15))*144 + (lane >> 4)*16;
    unsigned p_base = ps_u + (w*16 + (lane & 15))*144 + (lane >> 4)*16;
    unsigned k_base[4];
#pragma unroll
    for (int nf2 = 0; nf2 < 4; nf2++)
        k_base[nf2] = ks_u + (nf2*16 + (lane & 7) + ((lane >> 4) & 1)*8)*144 + ((lane >> 3) & 1)*16;
    unsigned v_row = (lane & 15)*144 + (lane >> 4)*16;

    load_kv(0);

    for (int kt = 0; kt < 17; kt++){
        __syncthreads();
        if (kt < 16) load_kv(kt + 1);
        if (kt < 16) cp_wait<1>(); else cp_wait<0>();
        __syncthreads();

        unsigned st = (unsigned)(kt & 1);
        unsigned kso = st*STGK*4, vso = st*STGK*4;
        int k0 = kt * 64;
        const float* kd = kdep + st*64;

        float S[8][4];
#pragma unroll
        for (int nf = 0; nf < 8; nf++)
#pragma unroll
            for (int r = 0; r < 4; r++) S[nf][r] = 0.f;
#pragma unroll
        for (int kf = 0; kf < 4; kf++){
            unsigned a0, a1, a2, a3;
            ldsm4(a0, a1, a2, a3, q_base + kf*32);
#pragma unroll
            for (int nf2 = 0; nf2 < 4; nf2++){
                unsigned b0, b1, b2, b3;
                ldsm4(b0, b1, b2, b3, k_base[nf2] + kso + kf*32);
                mma_bf16(S[nf2*2  ][0], S[nf2*2  ][1], S[nf2*2  ][2], S[nf2*2  ][3], a0,a1,a2,a3, b0,b1);
                mma_bf16(S[nf2*2+1][0], S[nf2*2+1][1], S[nf2*2+1][2], S[nf2*2+1][3], a0,a1,a2,a3, b2,b3);
            }
        }

        bool kval[8][2];
#pragma unroll
        for (int nf = 0; nf < 8; nf++){
#pragma unroll
            for (int j = 0; j < 2; j++){
                int kl = nf*8 + c*2 + j;
                int kn = k0 + kl;
                kval[nf][j] = (kn < CN);
                float ky, kx;
                tok_coord(kn, ky, kx);
                float kdv = kd[kl];
#pragma unroll
                for (int i = 0; i < 2; i++){
                    float pos = fabsf(qy[i]-ky) + fabsf(qx[i]-kx);
                    float vv = S[nf][i*2+j]*0.125f + w0*pos + w1*fabsf(qd[i]-kdv);
                    S[nf][i*2+j] = kval[nf][j] ? vv : -1e30f;
                }
            }
        }

        float alpha[2];
#pragma unroll
        for (int i = 0; i < 2; i++){
            float tm = -1e30f;
#pragma unroll
            for (int nf = 0; nf < 8; nf++){
                tm = fmaxf(tm, S[nf][i*2]);
                tm = fmaxf(tm, S[nf][i*2+1]);
            }
            tm = fmaxf(tm, __shfl_xor_sync(0xffffffffu, tm, 1));
            tm = fmaxf(tm, __shfl_xor_sync(0xffffffffu, tm, 2));
            float mn = fmaxf(mi[i], tm);
            alpha[i] = __expf(mi[i] - mn);
            float ssum = 0.f;
#pragma unroll
            for (int nf = 0; nf < 8; nf++){
#pragma unroll
                for (int j = 0; j < 2; j++){
                    float p = kval[nf][j] ? __expf(S[nf][i*2+j] - mn) : 0.f;
                    S[nf][i*2+j] = p;
                    ssum += p;
                }
            }
            ssum += __shfl_xor_sync(0xffffffffu, ssum, 1);
            ssum += __shfl_xor_sync(0xffffffffu, ssum, 2);
            li[i] = li[i]*alpha[i] + ssum;
            mi[i] = mn;
        }
#pragma unroll
        for (int nf = 0; nf < 8; nf++){
            O[nf][0] *= alpha[0]; O[nf][1] *= alpha[0];
            O[nf][2] *= alpha[1]; O[nf][3] *= alpha[1];
        }
        int rbase = w*16 + gr;
#pragma unroll
        for (int nf = 0; nf < 8; nf++){
#pragma unroll
            for (int i = 0; i < 2; i++){
                Ps[(rbase + i*8)*AST + nf*4 + c] = pack_bf(S[nf][i*2], S[nf][i*2+1]);
            }
        }
        __syncwarp();

#pragma unroll
        for (int kf = 0; kf < 4; kf++){
            unsigned a0, a1, a2, a3;
            ldsm4(a0, a1, a2, a3, p_base + kf*32);
#pragma unroll
            for (int dg = 0; dg < 4; dg++){
                unsigned b0, b1, b2, b3;
                ldsm4t(b0, b1, b2, b3, vs_u + vso + kf*16*144 + v_row + dg*32);
                mma_bf16(O[dg*2  ][0], O[dg*2  ][1], O[dg*2  ][2], O[dg*2  ][3], a0,a1,a2,a3, b0,b1);
                mma_bf16(O[dg*2+1][0], O[dg*2+1][1], O[dg*2+1][2], O[dg*2+1][3], a0,a1,a2,a3, b2,b3);
            }
        }
    }

#pragma unroll
    for (int i = 0; i < 2; i++){
        int qn = q0 + w*16 + gr + i*8;
        if (qn >= CN) continue;
        float invl = 1.f / li[i];
        size_t base = ((size_t)b*CN + qn)*CC + h*64;
#pragma unroll
        for (int nf = 0; nf < 8; nf++){
            int cc2 = nf*8 + c*2;
            ((unsigned*)ao)[(base + cc2) >> 1] = pack_bf(O[nf][i*2]*invl, O[nf][i*2+1]*invl);
        }
    }
}

// ---------------- final: out = fused + BN(op_pw output), with transpose (bf16 in) ----------
__global__ void k_final(const float* __restrict__ fused, const __nv_bfloat16* __restrict__ o2t,
                        const float* __restrict__ bn, float* __restrict__ out)
{
    __shared__ float tile[32][33];
    int b = blockIdx.z;
    int p0 = blockIdx.x * 32, c0 = blockIdx.y * 32;
    int tx = threadIdx.x, ty = threadIdx.y;
#pragma unroll
    for (int i = 0; i < 4; i++){
        int p = p0 + ty + i*8;
        tile[ty + i*8][tx] = __bfloat162float(o2t[((size_t)b*CHW + p)*CC + c0 + tx]);
    }
    __syncthreads();
#pragma unroll
    for (int i = 0; i < 4; i++){
        int c = c0 + ty + i*8;
        float s = bn[c] * rsqrtf(bn[3*CC+c] + EPS);
        float t = bn[CC+c] - bn[2*CC+c] * s;
        size_t idx = ((size_t)b*CC + c)*CHW + p0 + tx;
        out[idx] = fused[idx] + tile[tx][ty + i*8] * s + t;
    }
}

// ---------------- host ----------------
template<int EPI, int OBF>
static void gemm_go(const __nv_bfloat16* A, const __nv_bfloat16* Bw, void* Cm,
                    int M, int N, int K, const float* ep, const float* res)
{
    cudaFuncSetAttribute(k_gemm_bf<EPI,OBF>, cudaFuncAttributeMaxDynamicSharedMemorySize, GEMM_SMEM);
    dim3 g(N/64, (M + 127)/128);
    k_gemm_bf<EPI,OBF><<<g, 256, GEMM_SMEM>>>(A, Bw, Cm, M, N, K, ep, res);
}

extern "C" void kernel_launch(void* const* d_in, const int* in_sizes, int n_in,
                              void* d_out, int out_size)
{
    const float* fused        = (const float*)d_in[0];
    const float* depth        = (const float*)d_in[1];
    const float* pg_dw_w      = (const float*)d_in[2];
    const float* pg_bn1       = (const float*)d_in[3];
    const float* pg_pw_w      = (const float*)d_in[4];
    const float* pg_bn2       = (const float*)d_in[5];
    const float* prompt_embed = (const float*)d_in[6];
    const float* pg_ln        = (const float*)d_in[7];
    const float* gp_dw_w      = (const float*)d_in[8];
    const float* gp_bn        = (const float*)d_in[9];
    const float* gp_pw_w      = (const float*)d_in[10];
    const float* gp_pw_b      = (const float*)d_in[11];
    const float* gp_weight    = (const float*)d_in[12];
    const float* ln1          = (const float*)d_in[13];
    const float* wq           = (const float*)d_in[14];
    const float* wk           = (const float*)d_in[15];
    const float* wv           = (const float*)d_in[16];
    const float* wo           = (const float*)d_in[17];
    const float* ln2          = (const float*)d_in[18];
    const float* mlp_w1       = (const float*)d_in[19];
    const float* mlp_b1       = (const float*)d_in[20];
    const float* mlp_w2       = (const float*)d_in[21];
    const float* mlp_b2       = (const float*)d_in[22];
    const float* op_dw_w      = (const float*)d_in[23];
    const float* op_bn1       = (const float*)d_in[24];
    const float* op_pw_w      = (const float*)d_in[25];
    const float* op_bn2       = (const float*)d_in[26];

    float *ppool,*ds,*jdb,*jt;
    __nv_bfloat16 *pp1t,*pp2t,*xb,*qkv,*aob,*hb,*enh,*o1t,*o2tb,*wall;
    cudaGetSymbolAddress((void**)&ppool,g_ppool);
    cudaGetSymbolAddress((void**)&ds,   g_ds);
    cudaGetSymbolAddress((void**)&jdb,  g_jd);
    cudaGetSymbolAddress((void**)&jt,   g_jt);
    cudaGetSymbolAddress((void**)&pp1t, g_pp1t_bf);
    cudaGetSymbolAddress((void**)&pp2t, g_pp2t_bf);
    cudaGetSymbolAddress((void**)&xb,   g_x_bf);
    cudaGetSymbolAddress((void**)&qkv,  g_qkv_bf);
    cudaGetSymbolAddress((void**)&aob,  g_ao_bf);
    cudaGetSymbolAddress((void**)&hb,   g_h_bf);
    cudaGetSymbolAddress((void**)&enh,  g_enh_bf);
    cudaGetSymbolAddress((void**)&o1t,  g_o1t_bf);
    cudaGetSymbolAddress((void**)&o2tb, g_o2t_bf);
    cudaGetSymbolAddress((void**)&wall, g_wall);

    cudaFuncSetAttribute(k_attn, cudaFuncAttributeMaxDynamicSharedMemorySize, ATTN_SMEM);

    static cudaStream_t s1 = nullptr, s2 = nullptr;
    static cudaEvent_t evStart, evPack, evImg, evJd, evDw;
    if (!s1){
        cudaStreamCreateWithFlags(&s1, cudaStreamNonBlocking);
        cudaStreamCreateWithFlags(&s2, cudaStreamNonBlocking);
        cudaEventCreateWithFlags(&evStart, cudaEventDisableTiming);
        cudaEventCreateWithFlags(&evPack,  cudaEventDisableTiming);
        cudaEventCreateWithFlags(&evImg,   cudaEventDisableTiming);
        cudaEventCreateWithFlags(&evJd,    cudaEventDisableTiming);
        cudaEventCreateWithFlags(&evDw,    cudaEventDisableTiming);
    }

    dim3 tgrid(CHW/32, CC/32, CB), tblk(32, 8);

    // main: zero ds, fork
    cudaMemsetAsync(ds, 0, CB*CHW*sizeof(float), 0);
    cudaEventRecord(evStart, 0);

    // s1: weight pack (independent)
    cudaStreamWaitEvent(s1, evStart, 0);
    k_pack_all<<<(WALL/4 + 255)/256, 256, 0, s1>>>(pg_pw_w, wq, wk, wv, wo, mlp_w1, mlp_w2,
                                                   op_pw_w, wall);
    cudaEventRecord(evPack, s1);

    // s2: image tokens transpose (independent)
    cudaStreamWaitEvent(s2, evStart, 0);
    k_cp_to_tok_f<<<tgrid, tblk, 0, s2>>>(fused, jt, CN, NPR);
    cudaEventRecord(evImg, s2);

    // main: dual dwconv (+ gp projection into ds)
    k_dwconv_t<1,float><<<tgrid, tblk>>>(depth, pg_dw_w, pg_bn1, pp1t, gp_dw_w, gp_bn,
                                         gp_pw_w, ds);
    cudaEventRecord(evDw, 0);

    // s2: jd after dwconv (and after its own cp_to_tok)
    cudaStreamWaitEvent(s2, evDw, 0);
    k_jd<<<(CB*CN + 255)/256, 256, 0, s2>>>(ds, gp_pw_b, jdb);
    cudaEventRecord(evJd, s2);

    // main: pg GEMM (needs pack + dwconv) -> prompt chain
    cudaStreamWaitEvent(0, evPack, 0);
    gemm_go<1,1>(pp1t, wall + OPG, pp2t, CB*CHW, CC, CC, pg_bn2, nullptr);
    k_prompt_pool<<<dim3(8, NPR, CB), 256>>>(pp2t, ppool);
    k_prompt_ln<<<CB*NPR, 256>>>(ppool, prompt_embed, pg_ln, jt);

    // join image tokens, then attention block
    cudaStreamWaitEvent(0, evImg, 0);
    k_ln<<<CB*CN, 256>>>(jt, ln1, xb);
    gemm_go<0,1>(xb, wall + OQKV, qkv, CB*CN, QKV, CC, nullptr, nullptr);
    cudaStreamWaitEvent(0, evJd, 0);
    k_attn<<<dim3(9, CNH, CB), 256, ATTN_SMEM>>>(qkv, jdb, gp_weight, aob);
    gemm_go<4,0>(aob, wall + OWO, jt, CB*CN, CC, CC, nullptr, jt);

    // MLP
    k_ln<<<CB*CN, 256>>>(jt, ln2, xb);
    gemm_go<2,1>(xb, wall + OW1, hb, CB*CN, HID, CC, mlp_b1, nullptr);
    gemm_go<3,0>(hb, wall + OW2, jt, CB*CN, CC, HID, mlp_b2, jt);

    // out_proj
    k_tok_to_cp<<<tgrid, tblk>>>(jt, enh, CN, NPR);
    k_dwconv_t<0,__nv_bfloat16><<<tgrid, tblk>>>(enh, op_dw_w, op_bn1, o1t,
                                                 nullptr, nullptr, nullptr, nullptr);
    gemm_go<0,1>(o1t, wall + OWOP, o2tb, CB*CHW, CC, CC, nullptr, nullptr);
    k_final<<<tgrid, tblk>>>(fused, o2tb, op_bn2, (float*)d_out);
}

// round 17
// speedup vs baseline: 1.1001x; 1.1001x over previous
#include <cuda_runtime.h>
#include <cuda_bf16.h>
#include <cstdint>
#include <math.h>

// ---------------- problem constants ----------------
constexpr int CB  = 4;      // batch
constexpr int CC  = 512;    // channels
constexpr int CHH = 32;     // H
constexpr int CWW = 32;     // W
constexpr int CHW = 1024;   // H*W
constexpr int CNH = 8;      // heads
constexpr int NPR = 8;      // prompt tokens
constexpr int CN  = 1032;   // total tokens
constexpr int HID = 1024;   // mlp hidden
constexpr int QKV = 3*CC;   // fused qkv row stride
constexpr float EPS = 1e-5f;

// weight arena offsets (bf16 elements)
constexpr int OPG  = 0;
constexpr int OQKV = 262144;
constexpr int OWO  = OQKV + 3*262144;
constexpr int OW1  = OWO + 262144;
constexpr int OW2  = OW1 + 524288;
constexpr int OWOP = OW2 + 524288;
constexpr int WALL = OWOP + 262144;

// ---------------- scratch ----------------
__device__ __align__(16) float g_ppool[CB*NPR*8*CC];
__device__ __align__(16) float g_ds  [CB*CHW];
__device__ __align__(16) float g_jd  [CB*CN];
__device__ __align__(16) float g_jt  [CB*CN*CC];
__device__ __align__(16) __nv_bfloat16 g_pp1t_bf[CB*CHW*CC];
__device__ __align__(16) __nv_bfloat16 g_pp2t_bf[CB*CHW*CC];
__device__ __align__(16) __nv_bfloat16 g_x_bf  [CB*CN*CC];
__device__ __align__(16) __nv_bfloat16 g_qkv_bf[CB*CN*QKV];
__device__ __align__(16) __nv_bfloat16 g_ao_bf [CB*CN*CC];
__device__ __align__(16) __nv_bfloat16 g_h_bf  [CB*CN*HID];
__device__ __align__(16) __nv_bfloat16 g_enh_bf[CB*CC*CHW];
__device__ __align__(16) __nv_bfloat16 g_o1t_bf[CB*CHW*CC];
__device__ __align__(16) __nv_bfloat16 g_o2t_bf[CB*CHW*CC];
__device__ __align__(16) __nv_bfloat16 g_wall  [WALL];

__device__ __forceinline__ float gelu_f(float x){
    return 0.5f * x * (1.0f + erff(x * 0.70710678118654752f));
}
__device__ __forceinline__ unsigned pack_bf(float lo, float hi){
    unsigned r;
    asm("cvt.rn.bf16x2.f32 %0, %1, %2;" : "=r"(r) : "f"(hi), "f"(lo));
    return r;
}
__device__ __forceinline__ float ldf(const float* p){ return *p; }
__device__ __forceinline__ float ldf(const __nv_bfloat16* p){ return __bfloat162float(*p); }
__device__ __forceinline__ void mma_bf16(float& d0, float& d1, float& d2, float& d3,
                                         unsigned a0, unsigned a1, unsigned a2, unsigned a3,
                                         unsigned b0, unsigned b1)
{
    asm volatile("mma.sync.aligned.m16n8k16.row.col.f32.bf16.bf16.f32 "
                 "{%0,%1,%2,%3}, {%4,%5,%6,%7}, {%8,%9}, {%0,%1,%2,%3};"
                 : "+f"(d0), "+f"(d1), "+f"(d2), "+f"(d3)
                 : "r"(a0), "r"(a1), "r"(a2), "r"(a3), "r"(b0), "r"(b1));
}
__device__ __forceinline__ unsigned su32(const void* p){
    return (unsigned)__cvta_generic_to_shared(p);
}
__device__ __forceinline__ void ldsm4(unsigned& r0, unsigned& r1, unsigned& r2, unsigned& r3,
                                      unsigned addr){
    asm volatile("ldmatrix.sync.aligned.m8n8.x4.shared.b16 {%0,%1,%2,%3}, [%4];"
                 : "=r"(r0), "=r"(r1), "=r"(r2), "=r"(r3) : "r"(addr));
}
__device__ __forceinline__ void ldsm4t(unsigned& r0, unsigned& r1, unsigned& r2, unsigned& r3,
                                       unsigned addr){
    asm volatile("ldmatrix.sync.aligned.m8n8.x4.trans.shared.b16 {%0,%1,%2,%3}, [%4];"
                 : "=r"(r0), "=r"(r1), "=r"(r2), "=r"(r3) : "r"(addr));
}
__device__ __forceinline__ void cp16(unsigned dst, const void* src, bool v){
    int sz = v ? 16 : 0;
    asm volatile("cp.async.cg.shared.global [%0], [%1], 16, %2;" :: "r"(dst), "l"(src), "r"(sz));
}
__device__ __forceinline__ void cp_commit(){ asm volatile("cp.async.commit_group;"); }
template<int N>
__device__ __forceinline__ void cp_wait(){ asm volatile("cp.async.wait_group %0;" :: "n"(N)); }

// ---------------- single fused weight pack ----------------
__global__ void k_pack_all(const float* __restrict__ pg, const float* __restrict__ wq,
                           const float* __restrict__ wk, const float* __restrict__ wv,
                           const float* __restrict__ wo, const float* __restrict__ w1,
                           const float* __restrict__ w2, const float* __restrict__ wop,
                           __nv_bfloat16* __restrict__ d)
{
    int i = blockIdx.x * 256 + threadIdx.x;
    if (i >= WALL/4) return;
    int f = i * 4;
    const float* s; int base;
    if      (f < OQKV)              { s = pg;  base = OPG;  }
    else if (f < OQKV + 262144)     { s = wq;  base = OQKV; }
    else if (f < OQKV + 2*262144)   { s = wk;  base = OQKV + 262144; }
    else if (f < OWO)               { s = wv;  base = OQKV + 2*262144; }
    else if (f < OW1)               { s = wo;  base = OWO;  }
    else if (f < OW2)               { s = w1;  base = OW1;  }
    else if (f < OWOP)              { s = w2;  base = OW2;  }
    else                            { s = wop; base = OWOP; }
    float4 v = *(const float4*)(s + (f - base));
    *(uint2*)(d + f) = make_uint2(pack_bf(v.x, v.y), pack_bf(v.z, v.w));
}

// ------- fused depthwise 3x3 conv + BN + GELU + transpose-to-token (+ gp projection) -------
template<int DUAL, typename TIN>
__global__ void k_dwconv_t(const TIN* __restrict__ in,
                           const float* __restrict__ w1, const float* __restrict__ bn1,
                           __nv_bfloat16* __restrict__ out1t,
                           const float* __restrict__ w2, const float* __restrict__ bn2,
                           const float* __restrict__ gpw, float* __restrict__ ds)
{
    __shared__ float tile[32][33];
    __shared__ float red[8][33];
    int b = blockIdx.z;
    int p0 = blockIdx.x * 32, c0 = blockIdx.y * 32;
    int tx = threadIdx.x, ty = threadIdx.y;
    int p = p0 + tx, y = p >> 5, x = p & 31;
    float wsum = 0.f;
#pragma unroll
    for (int i = 0; i < 4; i++){
        int c = c0 + ty + i*8;
        const TIN* base = in + (((size_t)b*CC + c) << 10);
        float v[9];
#pragma unroll
        for (int ky = 0; ky < 3; ky++)
#pragma unroll
            for (int kx = 0; kx < 3; kx++){
                int yy = y + ky - 1, xx = x + kx - 1;
                v[ky*3+kx] = (yy >= 0 && yy < CHH && xx >= 0 && xx < CWW) ? ldf(base + yy*CWW + xx) : 0.f;
            }
        float a1 = 0.f;
#pragma unroll
        for (int k = 0; k < 9; k++) a1 += w1[c*9+k] * v[k];
        float s1 = bn1[c] * rsqrtf(bn1[3*CC+c] + EPS);
        a1 = a1 * s1 + bn1[CC+c] - bn1[2*CC+c] * s1;
        tile[ty + i*8][tx] = gelu_f(a1);
        if (DUAL){
            float a2 = 0.f;
#pragma unroll
            for (int k = 0; k < 9; k++) a2 += w2[c*9+k] * v[k];
            float s2 = bn2[c] * rsqrtf(bn2[3*CC+c] + EPS);
            a2 = a2 * s2 + bn2[CC+c] - bn2[2*CC+c] * s2;
            wsum += gpw[c] * gelu_f(a2);
        }
    }
    if (DUAL) red[ty][tx] = wsum;
    __syncthreads();
    if (DUAL && ty == 0){
        float s = 0.f;
#pragma unroll
        for (int z = 0; z < 8; z++) s += red[z][tx];
        atomicAdd(&ds[(b << 10) + p0 + tx], s);
    }
#pragma unroll
    for (int i = 0; i < 4; i++){
        int pp_ = p0 + ty + i*8;
        out1t[((size_t)b*CHW + pp_)*CC + c0 + tx] = __float2bfloat16(tile[tx][ty + i*8]);
    }
}

// ---------------- transposes ----------------
__global__ void k_cp_to_tok_f(const float* __restrict__ in, float* __restrict__ out,
                              int tokTotal, int tokOff)
{
    __shared__ float tile[32][33];
    int b = blockIdx.z;
    int p0 = blockIdx.x * 32, c0 = blockIdx.y * 32;
    int tx = threadIdx.x, ty = threadIdx.y;
#pragma unroll
    for (int i = 0; i < 4; i++){
        int c = c0 + ty + i*8;
        tile[ty + i*8][tx] = in[((size_t)b*CC + c)*CHW + p0 + tx];
    }
    __syncthreads();
#pragma unroll
    for (int i = 0; i < 4; i++){
        int p = p0 + ty + i*8;
        out[((size_t)b*tokTotal + tokOff + p)*CC + c0 + tx] = tile[tx][ty + i*8];
    }
}

__global__ void k_tok_to_cp(const float* __restrict__ in, __nv_bfloat16* __restrict__ out,
                            int tokTotal, int tokOff)
{
    __shared__ float tile[32][33];
    int b = blockIdx.z;
    int p0 = blockIdx.x * 32, c0 = blockIdx.y * 32;
    int tx = threadIdx.x, ty = threadIdx.y;
#pragma unroll
    for (int i = 0; i < 4; i++){
        int p = p0 + ty + i*8;
        tile[ty + i*8][tx] = in[((size_t)b*tokTotal + tokOff + p)*CC + c0 + tx];
    }
    __syncthreads();
#pragma unroll
    for (int i = 0; i < 4; i++){
        int c = c0 + ty + i*8;
        out[((size_t)b*CC + c)*CHW + p0 + tx] = __float2bfloat16(tile[tx][ty + i*8]);
    }
}

// ---------------- tensor-core NT GEMM: 128x128, bf16, 4-stage cp.async, ldmatrix ----------
constexpr int RSU   = 20;
constexpr int STG_U = 128*RSU;
constexpr int NSTG  = 4;
constexpr int GEMM_SMEM = NSTG*STG_U*2*4;   // 81920 B

template<int EPI, int OBF>
__global__ void __launch_bounds__(256) k_gemm_bf(const __nv_bfloat16* __restrict__ A,
                                                 const __nv_bfloat16* __restrict__ Bw,
                                                 void* __restrict__ Cout,
                                                 int M, int N, int K,
                                                 const float* __restrict__ ep,
                                                 const float* __restrict__ res)
{
    extern __shared__ unsigned gsm[];
    unsigned* As = gsm;
    unsigned* Bs = gsm + NSTG*STG_U;
    unsigned as_u = su32(As), bs_u = su32(Bs);

    int tid  = threadIdx.x;
    int lane = tid & 31;
    int w    = tid >> 5;
    int wm   = w >> 1;
    int wn   = w & 1;
    int m0 = blockIdx.y * 128, n0 = blockIdx.x * 128;

    int r0 = tid >> 2, c0 = (tid & 3);
    const char* Ap0 = (const char*)(A + (size_t)(m0 + r0)*K + c0*8);
    const char* Ap1 = (const char*)(A + (size_t)(m0 + r0 + 64)*K + c0*8);
    const char* Bp0 = (const char*)(Bw + (size_t)(n0 + r0)*K + c0*8);
    const char* Bp1 = (const char*)(Bw + (size_t)(n0 + r0 + 64)*K + c0*8);
    bool av0 = (m0 + r0) < M, av1 = (m0 + r0 + 64) < M;
    unsigned ad0 = as_u + ((r0*RSU + c0*4) << 2);
    unsigned ad1 = as_u + (((r0+64)*RSU + c0*4) << 2);
    unsigned bd0 = bs_u + ((r0*RSU + c0*4) << 2);
    unsigned bd1 = bs_u + (((r0+64)*RSU + c0*4) << 2);

    float acc[2][8][4];
#pragma unroll
    for (int mf = 0; mf < 2; mf++)
#pragma unroll
        for (int nf = 0; nf < 8; nf++)
#pragma unroll
            for (int r = 0; r < 4; r++) acc[mf][nf][r] = 0.f;

    int NK = K >> 5;

#pragma unroll
    for (int st = 0; st < NSTG-1; st++){
        unsigned so = (st*STG_U) << 2;
        size_t go = (size_t)(st*32) * 2;
        cp16(ad0 + so, Ap0 + go, av0 && st < NK);
        cp16(ad1 + so, Ap1 + go, av1 && st < NK);
        cp16(bd0 + so, Bp0 + go, st < NK);
        cp16(bd1 + so, Bp1 + go, st < NK);
        cp_commit();
    }

    int l7 = lane & 7;
    unsigned a_base[2], b_base[4];
    {
        int acol = ((lane >> 4) & 1) * 4;
        int ar = wm*32 + l7 + ((lane >> 3) & 1) * 8;
        a_base[0] = as_u + ((ar*RSU + acol) << 2);
        a_base[1] = as_u + (((ar+16)*RSU + acol) << 2);
        int bcol = ((lane >> 3) & 1) * 4;
        int brr  = wn*64 + l7 + (lane >> 4) * 8;
#pragma unroll
        for (int nf2 = 0; nf2 < 4; nf2++)
            b_base[nf2] = bs_u + (((brr + nf2*16)*RSU + bcol) << 2);
    }

    for (int kt = 0; kt < NK; kt++){
        cp_wait<NSTG-2>();
        __syncthreads();

        int nk = kt + NSTG - 1;
        if (nk < NK){
            unsigned so = ((nk % NSTG)*STG_U) << 2;
            size_t go = (size_t)(nk*32) * 2;
            cp16(ad0 + so, Ap0 + go, av0);
            cp16(ad1 + so, Ap1 + go, av1);
            cp16(bd0 + so, Bp0 + go, true);
            cp16(bd1 + so, Bp1 + go, true);
        }
        cp_commit();

        unsigned soff = ((unsigned)(kt % NSTG) * STG_U) << 2;
#pragma unroll
        for (int kf = 0; kf < 2; kf++){
            unsigned ko = soff + kf*32;
            unsigned a[2][4];
            ldsm4(a[0][0], a[0][1], a[0][2], a[0][3], a_base[0] + ko);
            ldsm4(a[1][0], a[1][1], a[1][2], a[1][3], a_base[1] + ko);
#pragma unroll
            for (int nf2 = 0; nf2 < 4; nf2++){
                unsigned b0, b1, b2, b3;
                ldsm4(b0, b1, b2, b3, b_base[nf2] + ko);
#pragma unroll
                for (int mf = 0; mf < 2; mf++){
                    mma_bf16(acc[mf][nf2*2  ][0], acc[mf][nf2*2  ][1], acc[mf][nf2*2  ][2], acc[mf][nf2*2  ][3],
                             a[mf][0], a[mf][1], a[mf][2], a[mf][3], b0, b1);
                    mma_bf16(acc[mf][nf2*2+1][0], acc[mf][nf2*2+1][1], acc[mf][nf2*2+1][2], acc[mf][nf2*2+1][3],
                             a[mf][0], a[mf][1], a[mf][2], a[mf][3], b2, b3);
                }
            }
        }
    }

#pragma unroll
    for (int mf = 0; mf < 2; mf++){
#pragma unroll
        for (int ri = 0; ri < 2; ri++){
            int row = m0 + wm*32 + mf*16 + (lane >> 2) + ri*8;
            if (row >= M) continue;
            size_t base = (size_t)row * N;
#pragma unroll
            for (int nf = 0; nf < 8; nf++){
                int col = n0 + wn*64 + nf*8 + 2*(lane & 3);
                float v0 = acc[mf][nf][ri*2 + 0];
                float v1 = acc[mf][nf][ri*2 + 1];
                if (EPI == 1){
                    float s0 = ep[col]   * rsqrtf(ep[3*N+col]   + EPS);
                    float s1 = ep[col+1] * rsqrtf(ep[3*N+col+1] + EPS);
                    v0 = gelu_f(v0 * s0 + ep[N+col]   - ep[2*N+col]   * s0);
                    v1 = gelu_f(v1 * s1 + ep[N+col+1] - ep[2*N+col+1] * s1);
                } else if (EPI == 2){
                    v0 = gelu_f(v0 + ep[col]);
                    v1 = gelu_f(v1 + ep[col+1]);
                } else if (EPI == 3){
                    float2 rr2 = *(const float2*)(res + base + col);
                    v0 = rr2.x + v0 + ep[col];
                    v1 = rr2.y + v1 + ep[col+1];
                } else if (EPI == 4){
                    float2 rr2 = *(const float2*)(res + base + col);
                    v0 = rr2.x + v0;
                    v1 = rr2.y + v1;
                }
                if (OBF){
                    ((unsigned*)Cout)[(base + col) >> 1] = pack_bf(v0, v1);
                } else {
                    *(float2*)((float*)Cout + base + col) = make_float2(v0, v1);
                }
            }
        }
    }
}

// ---------------- prompt pooling phase 1: partial sums (bf16 input) ----------------
__global__ void k_prompt_pool(const __nv_bfloat16* __restrict__ pp2t, float* __restrict__ pool)
{
    int chunk = blockIdx.x, pr = blockIdx.y, b = blockIdx.z;
    int iy = pr >> 2, ix = pr & 3;
    int t = threadIdx.x;
    float a0 = 0.f, a1 = 0.f;
#pragma unroll
    for (int py = 0; py < 2; py++)
#pragma unroll
        for (int px = 0; px < 8; px++){
            int p = (iy*16 + chunk*2 + py)*CWW + ix*8 + px;
            const __nv_bfloat16* base = pp2t + ((size_t)b*CHW + p)*CC;
            a0 += __bfloat162float(base[t]);
            a1 += __bfloat162float(base[t + 256]);
        }
    size_t o = (((size_t)(b*NPR + pr))*8 + chunk)*CC;
    pool[o + t]       = a0;
    pool[o + t + 256] = a1;
}

// ---------------- prompt phase 2: combine + embed + LN -> jt rows 0..7 ----------------
__global__ void k_prompt_ln(const float* __restrict__ pool, const float* __restrict__ pe,
                            const float* __restrict__ lnp, float* __restrict__ jt)
{
    int b = blockIdx.x >> 3, pr = blockIdx.x & 7;
    int t = threadIdx.x;
    const float* pb = pool + (((size_t)(b*NPR + pr))*8)*CC;
    float a0 = 0.f, a1 = 0.f;
#pragma unroll
    for (int ch = 0; ch < 8; ch++){
        a0 += pb[ch*CC + t];
        a1 += pb[ch*CC + t + 256];
    }
    a0 = a0 * (1.f/128.f) + pe[pr*CC + t];
    a1 = a1 * (1.f/128.f) + pe[pr*CC + t + 256];
    __shared__ float rs[256], rq[256];
    rs[t] = a0 + a1; rq[t] = a0*a0 + a1*a1;
    __syncthreads();
    for (int s = 128; s > 0; s >>= 1){
        if (t < s){ rs[t] += rs[t+s]; rq[t] += rq[t+s]; }
        __syncthreads();
    }
    float mean = rs[0] * (1.f/512.f);
    float var  = rq[0] * (1.f/512.f) - mean*mean;
    float inv  = rsqrtf(var + EPS);
    size_t o = ((size_t)b*CN + pr) * CC;
    jt[o + t]       = (a0 - mean) * inv * lnp[t]       + lnp[CC + t];
    jt[o + t + 256] = (a1 - mean) * inv * lnp[t + 256] + lnp[CC + t + 256];
}

// ---------------- joint depth scalar per token ----------------
__global__ void k_jd(const float* __restrict__ ds, const float* __restrict__ gpb,
                     float* __restrict__ jd)
{
    int t = blockIdx.x * 256 + threadIdx.x;
    if (t >= CB*CN) return;
    int b = t / CN, n = t % CN;
    float bias = gpb[0];
    if (n >= NPR){
        jd[t] = ds[b*CHW + (n - NPR)] + bias;
    } else {
        int iy = n >> 2, ix = n & 3;
        float acc = 0.f;
#pragma unroll
        for (int py = 0; py < 16; py++){
            const float4* r = (const float4*)(ds + b*CHW + (iy*16 + py)*CWW + ix*8);
            float4 v0 = r[0], v1 = r[1];
            acc += v0.x + v0.y + v0.z + v0.w + v1.x + v1.y + v1.z + v1.w;
        }
        jd[t] = acc * (1.f/128.f) + bias;
    }
}

// ---------------- layernorm over C per token (fp32 in, bf16 out) ----------------
__global__ void k_ln(const float* __restrict__ in, const float* __restrict__ p,
                     __nv_bfloat16* __restrict__ out)
{
    int tok = blockIdx.x;
    const float* row = in + (size_t)tok * CC;
    int t = threadIdx.x;
    float v0 = row[t], v1 = row[t + 256];
    __shared__ float rs[256], rq[256];
    rs[t] = v0 + v1; rq[t] = v0*v0 + v1*v1;
    __syncthreads();
    for (int s = 128; s > 0; s >>= 1){
        if (t < s){ rs[t] += rs[t+s]; rq[t] += rq[t+s]; }
        __syncthreads();
    }
    float mean = rs[0] * (1.f/512.f);
    float var  = rq[0] * (1.f/512.f) - mean*mean;
    float inv  = rsqrtf(var + EPS);
    size_t o = (size_t)tok * CC;
    out[o + t]       = __float2bfloat16((v0 - mean) * inv * p[t]       + p[CC + t]);
    out[o + t + 256] = __float2bfloat16((v1 - mean) * inv * p[t + 256] + p[CC + t + 256]);
}

// ---------------- attention: flash, bf16 mma.sync, ldmatrix, cp.async double-buffer --------
__device__ __forceinline__ void tok_coord(int n, float& cy, float& cx){
    if (n < NPR){ cy = (float)(n >> 2); cx = (float)(n & 3) * (1.f/3.f); }
    else { int m = n - NPR; cy = (float)(m >> 5) * (1.f/31.f); cx = (float)(m & 31) * (1.f/31.f); }
}

constexpr int AST  = 36;
constexpr int QS_OFF = 0;
constexpr int PS_OFF = 128*AST;
constexpr int KS_OFF = PS_OFF + 128*AST;
constexpr int STGK   = 64*AST;
constexpr int VS_OFF = KS_OFF + 2*STGK;
constexpr int KD_OFF = VS_OFF + 2*STGK;
constexpr int ATTN_SMEM = (KD_OFF + 128) * 4;

__global__ void __launch_bounds__(256) k_attn(const __nv_bfloat16* __restrict__ qkv,
                                              const float* __restrict__ jd,
                                              const float* __restrict__ gw,
                                              __nv_bfloat16* __restrict__ ao)
{
    extern __shared__ unsigned smu[];
    unsigned* Qs = smu + QS_OFF;
    unsigned* Ps = smu + PS_OFF;
    float*  kdep = (float*)(smu + KD_OFF);
    unsigned qs_u = su32(Qs), ps_u = su32(Ps);
    unsigned ks_u = su32(smu + KS_OFF), vs_u = su32(smu + VS_OFF);
    unsigned kd_u = su32(kdep);

    int b = blockIdx.z, h = blockIdx.y, q0 = blockIdx.x * 128;
    int tid = threadIdx.x, lane = tid & 31, w = tid >> 5;
    int c = lane & 3, gr = lane >> 2;

    const float decay = logf(1.f - exp2f(-1.f - 0.5f * (float)h));
    const float w0 = gw[0] * decay, w1 = gw[1] * decay;

#pragma unroll
    for (int j = 0; j < 4; j++){
        int i = tid + 256*j;
        int r = i >> 3, c4 = i & 7;
        int qn = q0 + r;
        uint4 v = (qn < CN) ? *(const uint4*)(qkv + ((size_t)b*CN + qn)*QKV + h*64 + c4*8)
                            : make_uint4(0,0,0,0);
        *(uint4*)&Qs[r*AST + c4*4] = v;
    }

    int lr = tid >> 3, lc = tid & 7;
    auto load_kv = [&](int kt){
        int k0 = kt * 64;
        unsigned st = (unsigned)(kt & 1);
#pragma unroll
        for (int j = 0; j < 2; j++){
            int r = lr + j*32;
            int n = k0 + r;
            bool val = (n < CN);
            const __nv_bfloat16* rowp = qkv + ((size_t)b*CN + n)*QKV + h*64;
            unsigned doff = st*STGK*4 + r*144 + lc*16;
            cp16(ks_u + doff, rowp + CC   + lc*8, val);
            cp16(vs_u + doff, rowp + 2*CC + lc*8, val);
        }
        if (tid < 16){
            bool val = (k0 + tid*4 + 4) <= CN;
            cp16(kd_u + st*256 + tid*16, jd + (size_t)b*CN + k0 + tid*4, val);
        }
        cp_commit();
    };

    float qy[2], qx[2], qd[2];
#pragma unroll
    for (int i = 0; i < 2; i++){
        int qn = q0 + w*16 + gr + i*8;
        if (qn < CN){ tok_coord(qn, qy[i], qx[i]); qd[i] = jd[b*CN + qn]; }
        else { qy[i] = qx[i] = qd[i] = 0.f; }
    }

    float O[8][4];
#pragma unroll
    for (int nf = 0; nf < 8; nf++)
#pragma unroll
        for (int r = 0; r < 4; r++) O[nf][r] = 0.f;
    float mi[2] = {-1e30f, -1e30f}, li[2] = {0.f, 0.f};

    unsigned q_base = qs_u + (w*16 + (lane & 15))*144 + (lane >> 4)*16;
    unsigned p_base = ps_u + (w*16 + (lane & 15))*144 + (lane >> 4)*16;
    unsigned k_base[4];
#pragma unroll
    for (int nf2 = 0; nf2 < 4; nf2++)
        k_base[nf2] = ks_u + (nf2*16 + (lane & 7) + ((lane >> 4) & 1)*8)*144 + ((lane >> 3) & 1)*16;
    unsigned v_row = (lane & 15)*144 + (lane >> 4)*16;

    load_kv(0);

    for (int kt = 0; kt < 17; kt++){
        __syncthreads();
        if (kt < 16) load_kv(kt + 1);
        if (kt < 16) cp_wait<1>(); else cp_wait<0>();
        __syncthreads();

        unsigned st = (unsigned)(kt & 1);
        unsigned kso = st*STGK*4, vso = st*STGK*4;
        int k0 = kt * 64;
        const float* kd = kdep + st*64;

        float S[8][4];
#pragma unroll
        for (int nf = 0; nf < 8; nf++)
#pragma unroll
            for (int r = 0; r < 4; r++) S[nf][r] = 0.f;
#pragma unroll
        for (int kf = 0; kf < 4; kf++){
            unsigned a0, a1, a2, a3;
            ldsm4(a0, a1, a2, a3, q_base + kf*32);
#pragma unroll
            for (int nf2 = 0; nf2 < 4; nf2++){
                unsigned b0, b1, b2, b3;
                ldsm4(b0, b1, b2, b3, k_base[nf2] + kso + kf*32);
                mma_bf16(S[nf2*2  ][0], S[nf2*2  ][1], S[nf2*2  ][2], S[nf2*2  ][3], a0,a1,a2,a3, b0,b1);
                mma_bf16(S[nf2*2+1][0], S[nf2*2+1][1], S[nf2*2+1][2], S[nf2*2+1][3], a0,a1,a2,a3, b2,b3);
            }
        }

        bool kval[8][2];
#pragma unroll
        for (int nf = 0; nf < 8; nf++){
#pragma unroll
            for (int j = 0; j < 2; j++){
                int kl = nf*8 + c*2 + j;
                int kn = k0 + kl;
                kval[nf][j] = (kn < CN);
                float ky, kx;
                tok_coord(kn, ky, kx);
                float kdv = kd[kl];
#pragma unroll
                for (int i = 0; i < 2; i++){
                    float pos = fabsf(qy[i]-ky) + fabsf(qx[i]-kx);
                    float vv = S[nf][i*2+j]*0.125f + w0*pos + w1*fabsf(qd[i]-kdv);
                    S[nf][i*2+j] = kval[nf][j] ? vv : -1e30f;
                }
            }
        }

        float alpha[2];
#pragma unroll
        for (int i = 0; i < 2; i++){
            float tm = -1e30f;
#pragma unroll
            for (int nf = 0; nf < 8; nf++){
                tm = fmaxf(tm, S[nf][i*2]);
                tm = fmaxf(tm, S[nf][i*2+1]);
            }
            tm = fmaxf(tm, __shfl_xor_sync(0xffffffffu, tm, 1));
            tm = fmaxf(tm, __shfl_xor_sync(0xffffffffu, tm, 2));
            float mn = fmaxf(mi[i], tm);
            alpha[i] = __expf(mi[i] - mn);
            float ssum = 0.f;
#pragma unroll
            for (int nf = 0; nf < 8; nf++){
#pragma unroll
                for (int j = 0; j < 2; j++){
                    float p = kval[nf][j] ? __expf(S[nf][i*2+j] - mn) : 0.f;
                    S[nf][i*2+j] = p;
                    ssum += p;
                }
            }
            ssum += __shfl_xor_sync(0xffffffffu, ssum, 1);
            ssum += __shfl_xor_sync(0xffffffffu, ssum, 2);
            li[i] = li[i]*alpha[i] + ssum;
            mi[i] = mn;
        }
#pragma unroll
        for (int nf = 0; nf < 8; nf++){
            O[nf][0] *= alpha[0]; O[nf][1] *= alpha[0];
            O[nf][2] *= alpha[1]; O[nf][3] *= alpha[1];
        }
        int rbase = w*16 + gr;
#pragma unroll
        for (int nf = 0; nf < 8; nf++){
#pragma unroll
            for (int i = 0; i < 2; i++){
                Ps[(rbase + i*8)*AST + nf*4 + c] = pack_bf(S[nf][i*2], S[nf][i*2+1]);
            }
        }
        __syncwarp();

#pragma unroll
        for (int kf = 0; kf < 4; kf++){
            unsigned a0, a1, a2, a3;
            ldsm4(a0, a1, a2, a3, p_base + kf*32);
#pragma unroll
            for (int dg = 0; dg < 4; dg++){
                unsigned b0, b1, b2, b3;
                ldsm4t(b0, b1, b2, b3, vs_u + vso + kf*16*144 + v_row + dg*32);
                mma_bf16(O[dg*2  ][0], O[dg*2  ][1], O[dg*2  ][2], O[dg*2  ][3], a0,a1,a2,a3, b0,b1);
                mma_bf16(O[dg*2+1][0], O[dg*2+1][1], O[dg*2+1][2], O[dg*2+1][3], a0,a1,a2,a3, b2,b3);
            }
        }
    }

#pragma unroll
    for (int i = 0; i < 2; i++){
        int qn = q0 + w*16 + gr + i*8;
        if (qn >= CN) continue;
        float invl = 1.f / li[i];
        size_t base = ((size_t)b*CN + qn)*CC + h*64;
#pragma unroll
        for (int nf = 0; nf < 8; nf++){
            int cc2 = nf*8 + c*2;
            ((unsigned*)ao)[(base + cc2) >> 1] = pack_bf(O[nf][i*2]*invl, O[nf][i*2+1]*invl);
        }
    }
}

// ---------------- final: out = fused + BN(op_pw output), with transpose (bf16 in) ----------
__global__ void k_final(const float* __restrict__ fused, const __nv_bfloat16* __restrict__ o2t,
                        const float* __restrict__ bn, float* __restrict__ out)
{
    __shared__ float tile[32][33];
    int b = blockIdx.z;
    int p0 = blockIdx.x * 32, c0 = blockIdx.y * 32;
    int tx = threadIdx.x, ty = threadIdx.y;
#pragma unroll
    for (int i = 0; i < 4; i++){
        int p = p0 + ty + i*8;
        tile[ty + i*8][tx] = __bfloat162float(o2t[((size_t)b*CHW + p)*CC + c0 + tx]);
    }
    __syncthreads();
#pragma unroll
    for (int i = 0; i < 4; i++){
        int c = c0 + ty + i*8;
        float s = bn[c] * rsqrtf(bn[3*CC+c] + EPS);
        float t = bn[CC+c] - bn[2*CC+c] * s;
        size_t idx = ((size_t)b*CC + c)*CHW + p0 + tx;
        out[idx] = fused[idx] + tile[tx][ty + i*8] * s + t;
    }
}

// ---------------- host ----------------
template<int EPI, int OBF>
static void gemm_go(const __nv_bfloat16* A, const __nv_bfloat16* Bw, void* Cm,
                    int M, int N, int K, const float* ep, const float* res)
{
    cudaFuncSetAttribute(k_gemm_bf<EPI,OBF>, cudaFuncAttributeMaxDynamicSharedMemorySize, GEMM_SMEM);
    dim3 g(N/128, (M + 127)/128);
    k_gemm_bf<EPI,OBF><<<g, 256, GEMM_SMEM>>>(A, Bw, Cm, M, N, K, ep, res);
}

extern "C" void kernel_launch(void* const* d_in, const int* in_sizes, int n_in,
                              void* d_out, int out_size)
{
    const float* fused        = (const float*)d_in[0];
    const float* depth        = (const float*)d_in[1];
    const float* pg_dw_w      = (const float*)d_in[2];
    const float* pg_bn1       = (const float*)d_in[3];
    const float* pg_pw_w      = (const float*)d_in[4];
    const float* pg_bn2       = (const float*)d_in[5];
    const float* prompt_embed = (const float*)d_in[6];
    const float* pg_ln        = (const float*)d_in[7];
    const float* gp_dw_w      = (const float*)d_in[8];
    const float* gp_bn        = (const float*)d_in[9];
    const float* gp_pw_w      = (const float*)d_in[10];
    const float* gp_pw_b      = (const float*)d_in[11];
    const float* gp_weight    = (const float*)d_in[12];
    const float* ln1          = (const float*)d_in[13];
    const float* wq           = (const float*)d_in[14];
    const float* wk           = (const float*)d_in[15];
    const float* wv           = (const float*)d_in[16];
    const float* wo           = (const float*)d_in[17];
    const float* ln2          = (const float*)d_in[18];
    const float* mlp_w1       = (const float*)d_in[19];
    const float* mlp_b1       = (const float*)d_in[20];
    const float* mlp_w2       = (const float*)d_in[21];
    const float* mlp_b2       = (const float*)d_in[22];
    const float* op_dw_w      = (const float*)d_in[23];
    const float* op_bn1       = (const float*)d_in[24];
    const float* op_pw_w      = (const float*)d_in[25];
    const float* op_bn2       = (const float*)d_in[26];

    float *ppool,*ds,*jdb,*jt;
    __nv_bfloat16 *pp1t,*pp2t,*xb,*qkv,*aob,*hb,*enh,*o1t,*o2tb,*wall;
    cudaGetSymbolAddress((void**)&ppool,g_ppool);
    cudaGetSymbolAddress((void**)&ds,   g_ds);
    cudaGetSymbolAddress((void**)&jdb,  g_jd);
    cudaGetSymbolAddress((void**)&jt,   g_jt);
    cudaGetSymbolAddress((void**)&pp1t, g_pp1t_bf);
    cudaGetSymbolAddress((void**)&pp2t, g_pp2t_bf);
    cudaGetSymbolAddress((void**)&xb,   g_x_bf);
    cudaGetSymbolAddress((void**)&qkv,  g_qkv_bf);
    cudaGetSymbolAddress((void**)&aob,  g_ao_bf);
    cudaGetSymbolAddress((void**)&hb,   g_h_bf);
    cudaGetSymbolAddress((void**)&enh,  g_enh_bf);
    cudaGetSymbolAddress((void**)&o1t,  g_o1t_bf);
    cudaGetSymbolAddress((void**)&o2tb, g_o2t_bf);
    cudaGetSymbolAddress((void**)&wall, g_wall);

    cudaFuncSetAttribute(k_attn, cudaFuncAttributeMaxDynamicSharedMemorySize, ATTN_SMEM);

    static cudaStream_t s1 = nullptr, s2 = nullptr;
    static cudaEvent_t evStart, evPack, evImg, evJd, evDw;
    if (!s1){
        cudaStreamCreateWithFlags(&s1, cudaStreamNonBlocking);
        cudaStreamCreateWithFlags(&s2, cudaStreamNonBlocking);
        cudaEventCreateWithFlags(&evStart, cudaEventDisableTiming);
        cudaEventCreateWithFlags(&evPack,  cudaEventDisableTiming);
        cudaEventCreateWithFlags(&evImg,   cudaEventDisableTiming);
        cudaEventCreateWithFlags(&evJd,    cudaEventDisableTiming);
        cudaEventCreateWithFlags(&evDw,    cudaEventDisableTiming);
    }

    dim3 tgrid(CHW/32, CC/32, CB), tblk(32, 8);

    // main: zero ds, fork
    cudaMemsetAsync(ds, 0, CB*CHW*sizeof(float), 0);
    cudaEventRecord(evStart, 0);

    // s1: weight pack (independent)
    cudaStreamWaitEvent(s1, evStart, 0);
    k_pack_all<<<(WALL/4 + 255)/256, 256, 0, s1>>>(pg_pw_w, wq, wk, wv, wo, mlp_w1, mlp_w2,
                                                   op_pw_w, wall);
    cudaEventRecord(evPack, s1);

    // s2: image tokens transpose (independent)
    cudaStreamWaitEvent(s2, evStart, 0);
    k_cp_to_tok_f<<<tgrid, tblk, 0, s2>>>(fused, jt, CN, NPR);
    cudaEventRecord(evImg, s2);

    // main: dual dwconv (+ gp projection into ds)
    k_dwconv_t<1,float><<<tgrid, tblk>>>(depth, pg_dw_w, pg_bn1, pp1t, gp_dw_w, gp_bn,
                                         gp_pw_w, ds);
    cudaEventRecord(evDw, 0);

    // s2: jd after dwconv (and after its own cp_to_tok)
    cudaStreamWaitEvent(s2, evDw, 0);
    k_jd<<<(CB*CN + 255)/256, 256, 0, s2>>>(ds, gp_pw_b, jdb);
    cudaEventRecord(evJd, s2);

    // main: pg GEMM (needs pack + dwconv) -> prompt chain
    cudaStreamWaitEvent(0, evPack, 0);
    gemm_go<1,1>(pp1t, wall + OPG, pp2t, CB*CHW, CC, CC, pg_bn2, nullptr);
    k_prompt_pool<<<dim3(8, NPR, CB), 256>>>(pp2t, ppool);
    k_prompt_ln<<<CB*NPR, 256>>>(ppool, prompt_embed, pg_ln, jt);

    // join image tokens, then attention block
    cudaStreamWaitEvent(0, evImg, 0);
    k_ln<<<CB*CN, 256>>>(jt, ln1, xb);
    gemm_go<0,1>(xb, wall + OQKV, qkv, CB*CN, QKV, CC, nullptr, nullptr);
    cudaStreamWaitEvent(0, evJd, 0);
    k_attn<<<dim3(9, CNH, CB), 256, ATTN_SMEM>>>(qkv, jdb, gp_weight, aob);
    gemm_go<4,0>(aob, wall + OWO, jt, CB*CN, CC, CC, nullptr, jt);

    // MLP
    k_ln<<<CB*CN, 256>>>(jt, ln2, xb);
    gemm_go<2,1>(xb, wall + OW1, hb, CB*CN, HID, CC, mlp_b1, nullptr);
    gemm_go<3,0>(hb, wall + OW2, jt, CB*CN, CC, HID, mlp_b2, jt);

    // out_proj
    k_tok_to_cp<<<tgrid, tblk>>>(jt, enh, CN, NPR);
    k_dwconv_t<0,__nv_bfloat16><<<tgrid, tblk>>>(enh, op_dw_w, op_bn1, o1t,
                                                 nullptr, nullptr, nullptr, nullptr);
    gemm_go<0,1>(o1t, wall + OWOP, o2tb, CB*CHW, CC, CC, nullptr, nullptr);
    k_final<<<tgrid, tblk>>>(fused, o2tb, op_bn2, (float*)d_out);
}